// round 3
// baseline (speedup 1.0000x reference)
#include <cuda_runtime.h>
#include <math.h>

// Cox partial-likelihood loss, N = 8192 — single fused launch.
//   risk_sum[i] = sum_j exp(theta_j) * (t_j >= t_i)
//   loss = -(1/N) * sum_i (theta_i - log(risk_sum[i])) * censor_i
//
// Grid (GX=16 i-tiles, NBJ=16 j-chunks), 256 threads, 2 i per thread.
// Phase 1: block (bi,cj) stages j-chunk {t, exp(theta)} in shared (fused exp),
//          accumulates partial risk sums for its 512 i's, writes g_rpart.
// Phase 2: last-arriving block per i-tile (atomic counter) combines the 16
//          partials in fixed order, applies log/censor, block-reduces, writes
//          g_bsum[bi]. Very last block folds 16 tile sums in fixed order.
// All float sums are fixed-order -> bit-deterministic. Counters self-reset
// for graph replay. No allocations (device globals only).

#define COX_N   8192
#define IB      256                 // threads per block
#define IPT     2                   // i per thread
#define IBLK    (IB * IPT)          // 512 i per block
#define GX      (COX_N / IBLK)      // 16 i-tiles
#define NBJ     16                  // j-chunks
#define JC      (COX_N / NBJ)       // 512 j per chunk

__device__ float g_rpart[NBJ * COX_N];   // partial risk sums
__device__ float g_bsum[GX];             // per-i-tile loss partials
__device__ int   g_tile_count[GX];       // zero-initialized; self-resetting
__device__ int   g_final_count = 0;      // self-resetting

__global__ __launch_bounds__(IB) void cox_fused(const float* __restrict__ y_true,
                                                const float* __restrict__ hazard,
                                                float* __restrict__ out) {
    // float4-aligned shared: pairs of {t_j, e_j}.
    __shared__ float4 sh4[JC / 2];          // 4KB
    __shared__ float  red[IB];
    __shared__ int    s_last;

    float2* sh = (float2*)sh4;

    const int bi   = blockIdx.x;            // i-tile
    const int cj   = blockIdx.y;            // j-chunk
    const int tid  = threadIdx.x;
    const int base = cj * JC;

    // ---- Phase 1: stage chunk with fused exp ----
    for (int k = tid; k < JC; k += IB) {
        sh[k] = make_float2(y_true[2 * (base + k)], expf(hazard[base + k]));
    }
    __syncthreads();

    const int   i0 = bi * IBLK + tid;
    const int   i1 = i0 + IB;
    const float t0 = y_true[2 * i0];
    const float t1 = y_true[2 * i1];

    float s00 = 0.f, s01 = 0.f, s10 = 0.f, s11 = 0.f;
    #pragma unroll 8
    for (int k = 0; k < JC / 2; k++) {
        float4 v = sh4[k];                  // {t_j, e_j, t_j+1, e_j+1}
        if (v.x >= t0) s00 += v.y;
        if (v.x >= t1) s01 += v.y;
        if (v.z >= t0) s10 += v.w;
        if (v.z >= t1) s11 += v.w;
    }

    g_rpart[cj * COX_N + i0] = s00 + s10;
    g_rpart[cj * COX_N + i1] = s01 + s11;

    // ---- Arrival: is this the last j-chunk block for i-tile bi? ----
    __threadfence();                        // publish g_rpart writes
    __syncthreads();                        // all threads' stores issued before tid0 arrives
    if (tid == 0) {
        int prev = atomicAdd(&g_tile_count[bi], 1);
        s_last = (prev == NBJ - 1);
        if (s_last) g_tile_count[bi] = 0;   // safe: we were the last arrival
    }
    __syncthreads();
    if (!s_last) return;

    // ---- Phase 2: epilogue for this i-tile (one block per bi) ----
    __threadfence();                        // acquire other blocks' g_rpart
    float acc = 0.0f;
    #pragma unroll
    for (int u = 0; u < IPT; u++) {
        int i = bi * IBLK + u * IB + tid;
        float risk = 0.0f;
        #pragma unroll
        for (int c = 0; c < NBJ; c++) {
            risk += g_rpart[c * COX_N + i];           // fixed order
        }
        float cen = y_true[2 * i + 1];
        acc += (cen != 0.0f) ? (hazard[i] - logf(risk)) : 0.0f;
    }

    red[tid] = acc;
    __syncthreads();
    #pragma unroll
    for (int s = IB / 2; s > 0; s >>= 1) {
        if (tid < s) red[tid] += red[tid + s];
        __syncthreads();
    }

    if (tid == 0) {
        g_bsum[bi] = red[0];
        __threadfence();
        int prev = atomicAdd(&g_final_count, 1);
        if (prev == GX - 1) {
            __threadfence();
            float tot = 0.0f;
            #pragma unroll
            for (int b = 0; b < GX; b++) tot += g_bsum[b];   // fixed order
            out[0] = -tot / (float)COX_N;
            g_final_count = 0;              // reset for next graph replay
        }
    }
}

extern "C" void kernel_launch(void* const* d_in, const int* in_sizes, int n_in,
                              void* d_out, int out_size) {
    const float* y_true = (const float*)d_in[0];
    const float* hazard = (const float*)d_in[1];
    if (n_in >= 2 && in_sizes[0] < in_sizes[1]) {   // defensive order check
        y_true = (const float*)d_in[1];
        hazard = (const float*)d_in[0];
    }
    float* out = (float*)d_out;

    dim3 grid(GX, NBJ);
    cox_fused<<<grid, IB>>>(y_true, hazard, out);
}

// round 4
// speedup vs baseline: 1.2318x; 1.2318x over previous
#include <cuda_runtime.h>
#include <math.h>

// Cox partial-likelihood loss, N = 8192 — single fused launch.
//   risk_sum[i] = sum_j exp(theta_j) * (t_j >= t_i)
//   loss = -(1/N) * sum_i (theta_i - log(risk_sum[i])) * censor_i
//
// Load-balance-first design: 1024 small blocks (128 thr) over 148 SMs
// (~7 blocks/SM -> <=14% imbalance vs ~100% with 256 big blocks).
// Grid (GX=32 i-tiles, NBJ=32 j-chunks); 2 i per thread; FSEL-form inner loop.
// Last-arriving block per i-tile does that tile's epilogue; very last block
// folds tile sums in fixed order. All FP sums fixed-order -> deterministic.
// Counters self-reset for graph replay. No allocations (device globals only).

#define COX_N   8192
#define IB      128                 // threads per block
#define IPT     2                   // i per thread
#define IBLK    (IB * IPT)          // 256 i per block
#define GX      (COX_N / IBLK)      // 32 i-tiles
#define NBJ     32                  // j-chunks
#define JC      (COX_N / NBJ)       // 256 j per chunk

__device__ float g_rpart[NBJ * COX_N];   // partial risk sums (1MB)
__device__ float g_bsum[GX];             // per-i-tile loss partials
__device__ int   g_tile_count[GX];       // zero-init; self-resetting
__device__ int   g_final_count = 0;      // self-resetting

__global__ __launch_bounds__(IB) void cox_fused(const float* __restrict__ y_true,
                                                const float* __restrict__ hazard,
                                                float* __restrict__ out) {
    __shared__ float4 sh4[JC / 2];          // {t0,e0,t1,e1} pairs (2KB)
    __shared__ float  red[IB];
    __shared__ int    s_last;

    float2* sh = (float2*)sh4;

    const int bi   = blockIdx.x;            // i-tile
    const int cj   = blockIdx.y;            // j-chunk
    const int tid  = threadIdx.x;
    const int base = cj * JC;

    // ---- Phase 1: stage chunk with fused exp ----
    #pragma unroll
    for (int k = tid; k < JC; k += IB) {
        sh[k] = make_float2(y_true[2 * (base + k)], expf(hazard[base + k]));
    }
    __syncthreads();

    const int   i0 = bi * IBLK + tid;
    const int   i1 = i0 + IB;
    const float t0 = y_true[2 * i0];
    const float t1 = y_true[2 * i1];

    // FSEL + FADD form: balanced alu/fma dual issue, no predicate guards.
    float s00 = 0.f, s01 = 0.f, s10 = 0.f, s11 = 0.f;
    #pragma unroll 8
    for (int k = 0; k < JC / 2; k++) {
        float4 v = sh4[k];                  // {t_j, e_j, t_j+1, e_j+1}
        s00 += (v.x >= t0) ? v.y : 0.0f;
        s01 += (v.x >= t1) ? v.y : 0.0f;
        s10 += (v.z >= t0) ? v.w : 0.0f;
        s11 += (v.z >= t1) ? v.w : 0.0f;
    }

    g_rpart[cj * COX_N + i0] = s00 + s10;
    g_rpart[cj * COX_N + i1] = s01 + s11;

    // ---- Arrival: last j-chunk block for this i-tile runs the epilogue ----
    __threadfence();                        // publish g_rpart writes
    __syncthreads();                        // all stores issued before arrival
    if (tid == 0) {
        int prev = atomicAdd(&g_tile_count[bi], 1);
        s_last = (prev == NBJ - 1);
        if (s_last) g_tile_count[bi] = 0;   // safe: we were last
    }
    __syncthreads();
    if (!s_last) return;

    // ---- Phase 2: epilogue for i-tile bi ----
    __threadfence();                        // acquire other blocks' g_rpart
    float acc = 0.0f;
    #pragma unroll
    for (int u = 0; u < IPT; u++) {
        int i = bi * IBLK + u * IB + tid;
        float risk = 0.0f;
        #pragma unroll
        for (int c = 0; c < NBJ; c++) {
            risk += g_rpart[c * COX_N + i];           // fixed order
        }
        float cen = y_true[2 * i + 1];
        acc += (cen != 0.0f) ? (hazard[i] - logf(risk)) : 0.0f;
    }

    red[tid] = acc;
    __syncthreads();
    #pragma unroll
    for (int s = IB / 2; s > 0; s >>= 1) {
        if (tid < s) red[tid] += red[tid + s];
        __syncthreads();
    }

    if (tid == 0) {
        g_bsum[bi] = red[0];
        __threadfence();
        int prev = atomicAdd(&g_final_count, 1);
        if (prev == GX - 1) {
            __threadfence();
            float tot = 0.0f;
            #pragma unroll
            for (int b = 0; b < GX; b++) tot += g_bsum[b];   // fixed order
            out[0] = -tot / (float)COX_N;
            g_final_count = 0;              // reset for next graph replay
        }
    }
}

extern "C" void kernel_launch(void* const* d_in, const int* in_sizes, int n_in,
                              void* d_out, int out_size) {
    const float* y_true = (const float*)d_in[0];
    const float* hazard = (const float*)d_in[1];
    if (n_in >= 2 && in_sizes[0] < in_sizes[1]) {   // defensive order check
        y_true = (const float*)d_in[1];
        hazard = (const float*)d_in[0];
    }
    float* out = (float*)d_out;

    dim3 grid(GX, NBJ);
    cox_fused<<<grid, IB>>>(y_true, hazard, out);
}